// round 4
// baseline (speedup 1.0000x reference)
#include <cuda_runtime.h>
#include <stdint.h>

#define FULLMASK 0xFFFFFFFFu
#define NBATCH 16
#define NPT 2048
#define KNNK 20
#define EPSV 1e-5f
#define NEGINF (__int_as_float(0xff800000))

typedef unsigned long long u64;

// scratch (device globals: no allocation allowed)
__device__ float g_Ys[NBATCH * NPT * 32];
__device__ float g_Ps[NBATCH * NPT * 32];
__device__ int   g_knn[NBATCH * NPT * KNNK];

// ---- packed f32x2 helpers ----
__device__ __forceinline__ u64 pack2(float a, float b) {
    u64 r; asm("mov.b64 %0, {%1, %2};" : "=l"(r) : "f"(a), "f"(b)); return r;
}
__device__ __forceinline__ void unpack2(u64 v, float& a, float& b) {
    asm("mov.b64 {%0, %1}, %2;" : "=f"(a), "=f"(b) : "l"(v));
}
__device__ __forceinline__ u64 fma2(u64 a, u64 b, u64 c) {
    u64 d; asm("fma.rn.f32x2 %0, %1, %2, %3;" : "=l"(d) : "l"(a), "l"(b), "l"(c)); return d;
}
__device__ __forceinline__ u64 mul2(u64 a, u64 b) {
    u64 d; asm("mul.rn.f32x2 %0, %1, %2;" : "=l"(d) : "l"(a), "l"(b)); return d;
}
__device__ __forceinline__ u64 add2(u64 a, u64 b) {
    u64 d; asm("add.rn.f32x2 %0, %1, %2;" : "=l"(d) : "l"(a), "l"(b)); return d;
}

// monotone u32 transform of float (order-preserving)
__device__ __forceinline__ unsigned monot(float v) {
    unsigned u = __float_as_uint(v);
    return u ^ ((unsigned)(((int)u) >> 31) | 0x80000000u);
}

// insert (pd, j) into sorted-desc top-3 (strict >: earlier insert wins ties)
__device__ __forceinline__ void ins3(float& v1, float& v2, float& v3,
                                     int& i1, int& i2, int& i3, float pd, int j) {
    if (pd > v3) {
        if (pd > v2) {
            v3 = v2; i3 = i2;
            if (pd > v1) { v2 = v1; i2 = i1; v1 = pd; i1 = j; }
            else { v2 = pd; i2 = j; }
        } else { v3 = pd; i3 = j; }
    }
}

// -------- KNN: warp/row, SoA smem, packed distances, dual top-3, REDUX select --------
__global__ __launch_bounds__(256) void knn_kernel(const float* __restrict__ xyz) {
    __shared__ __align__(16) float sx[NPT], sy[NPT], sz[NPT], snw[NPT];
    int b = blockIdx.x >> 6;          // 64 blocks per batch
    int chunk = blockIdx.x & 63;      // 32 rows per block
    const float* xb = xyz + (size_t)b * 3 * NPT;
    for (int i = threadIdx.x; i < NPT; i += 256) {
        float x = xb[i], y = xb[NPT + i], z = xb[2 * NPT + i];
        sx[i] = x; sy[i] = y; sz[i] = z;
        snw[i] = -(x * x + y * y + z * z);
    }
    __syncthreads();
    int warp = threadIdx.x >> 5, lane = threadIdx.x & 31;
    const u64 two2 = pack2(2.0f, 2.0f);
    #pragma unroll 1
    for (int rr = 0; rr < 4; rr++) {
        int n = chunk * 32 + warp * 4 + rr;
        float cx = sx[n], cy = sy[n], cz = sz[n];
        u64 cx2 = pack2(cx, cx), cy2 = pack2(cy, cy), cz2 = pack2(cz, cz);
        u64 bb2 = pack2(snw[n], snw[n]);
        float va1 = NEGINF, va2 = NEGINF, va3 = NEGINF;
        float vb1 = NEGINF, vb2 = NEGINF, vb3 = NEGINF;
        int ia1 = 0, ia2 = 0, ia3 = 0, ib1 = 0, ib2 = 0, ib3 = 0;
        #pragma unroll 4
        for (int t = 0; t < 32; t++) {
            int jj = t * 64 + 2 * lane;
            u64 px = *(const u64*)(sx + jj);
            u64 py = *(const u64*)(sy + jj);
            u64 pz = *(const u64*)(sz + jj);
            u64 pw = *(const u64*)(snw + jj);
            u64 dot2 = fma2(cz2, pz, fma2(cy2, py, mul2(cx2, px)));
            u64 pd2 = fma2(two2, dot2, add2(pw, bb2));  // 2*dot - xx_i - xx_j
            float pl, ph; unpack2(pd2, pl, ph);
            ins3(va1, va2, va3, ia1, ia2, ia3, pl, jj);
            ins3(vb1, vb2, vb3, ib1, ib2, ib3, ph, jj + 1);
        }
        // merge the two sorted-desc lists into one top-3 (value desc, idx asc on tie)
        float v1, v2, v3; int i1, i2, i3;
        {
            bool pA = (va1 > vb1) || (va1 == vb1 && ia1 < ib1);
            v1 = pA ? va1 : vb1; i1 = pA ? ia1 : ib1;
            if (pA) { va1 = va2; ia1 = ia2; va2 = va3; ia2 = ia3; va3 = NEGINF; }
            else    { vb1 = vb2; ib1 = ib2; vb2 = vb3; ib2 = ib3; vb3 = NEGINF; }
            pA = (va1 > vb1) || (va1 == vb1 && ia1 < ib1);
            v2 = pA ? va1 : vb1; i2 = pA ? ia1 : ib1;
            if (pA) { va1 = va2; ia1 = ia2; }
            else    { vb1 = vb2; ib1 = ib2; }
            pA = (va1 > vb1) || (va1 == vb1 && ia1 < ib1);
            v3 = pA ? va1 : vb1; i3 = pA ? ia1 : ib1;
        }
        float lastV = 0.f; int lastI = 0;
        int myout = 0;
        #pragma unroll 1
        for (int r = 0; r < KNNK; r++) {
            unsigned key = monot(v1);
            unsigned mx = __reduce_max_sync(FULLMASK, key);
            unsigned lo = (key == mx) ? (unsigned)(NPT - 1 - i1) : 0u;
            unsigned lx = __reduce_max_sync(FULLMASK, lo);
            if (lane == r) myout = NPT - 1 - (int)lx;
            if (key == mx && lo == lx) {          // unique winner pops
                lastV = v1; lastI = i1;
                v1 = v2; i1 = i2; v2 = v3; i2 = i3; v3 = NEGINF; i3 = 0;
                if (v1 == NEGINF) {               // cache exhausted: rescan (rare)
                    #pragma unroll 4
                    for (int t = 0; t < 32; t++) {
                        int jj = t * 64 + 2 * lane;
                        u64 px = *(const u64*)(sx + jj);
                        u64 py = *(const u64*)(sy + jj);
                        u64 pz = *(const u64*)(sz + jj);
                        u64 pw = *(const u64*)(snw + jj);
                        u64 dot2 = fma2(cz2, pz, fma2(cy2, py, mul2(cx2, px)));
                        u64 pd2 = fma2(two2, dot2, add2(pw, bb2));
                        float pl, ph; unpack2(pd2, pl, ph);
                        if ((pl < lastV) || (pl == lastV && jj > lastI))
                            ins3(v1, v2, v3, i1, i2, i3, pl, jj);
                        if ((ph < lastV) || (ph == lastV && jj + 1 > lastI))
                            ins3(v1, v2, v3, i1, i2, i3, ph, jj + 1);
                    }
                }
            }
        }
        if (lane < KNNK) g_knn[(b * NPT + n) * KNNK + lane] = myout;  // coalesced
    }
}

// ------- precompute: packed (Ys, Ps) via pre-scaled packed weights, 4 acc chains -------
__global__ __launch_bounds__(256) void pre_kernel(
    const float* __restrict__ xf, const float* __restrict__ W1,
    const float* __restrict__ g1, const float* __restrict__ b1,
    const float* __restrict__ m1, const float* __restrict__ v1) {
    __shared__ u64 W1P[128 * 32];  // [c][o]: (wa*s, (wb-wa)*s)
    for (int i = threadIdx.x; i < 4096; i += 256) {
        int o = i & 31, cc = i >> 5;
        float s = g1[o] * rsqrtf(v1[o] + EPSV);
        float wa = W1[o * 128 + cc], wb = W1[o * 128 + 64 + cc];
        W1P[cc * 32 + o] = pack2(wa * s, (wb - wa) * s);
    }
    __syncthreads();
    int warp = threadIdx.x >> 5, lane = threadIdx.x & 31;
    float s = g1[lane] * rsqrtf(v1[lane] + EPSV);
    float shift = fmaf(-m1[lane], s, b1[lane]);
    #pragma unroll 1
    for (int pp = 0; pp < 8; pp++) {
        int point = blockIdx.x * 64 + warp * 8 + pp;
        int b = point >> 11, n = point & (NPT - 1);
        const float* col = xf + (size_t)b * 64 * NPT + n;
        u64 a0 = 0, a1 = 0, a2 = 0, a3 = 0;
        #pragma unroll
        for (int cc = 0; cc < 64; cc += 4) {
            float x0 = col[(size_t)cc * NPT];
            float x1 = col[(size_t)(cc + 1) * NPT];
            float x2 = col[(size_t)(cc + 2) * NPT];
            float x3 = col[(size_t)(cc + 3) * NPT];
            a0 = fma2(W1P[cc * 32 + lane],       pack2(x0, x0), a0);
            a1 = fma2(W1P[(cc + 1) * 32 + lane], pack2(x1, x1), a1);
            a2 = fma2(W1P[(cc + 2) * 32 + lane], pack2(x2, x2), a2);
            a3 = fma2(W1P[(cc + 3) * 32 + lane], pack2(x3, x3), a3);
        }
        float y, p; unpack2(add2(add2(a0, a1), add2(a2, a3)), y, p);
        g_Ys[point * 32 + lane] = y;
        g_Ps[point * 32 + lane] = p + shift;
    }
}

// ---- edge MLP: staged phases (2 syncwarps/point), FFMA2 GEMVs with split chains ----
__global__ __launch_bounds__(128) void mlp_kernel(
    const float* __restrict__ W2, const float* __restrict__ g2,
    const float* __restrict__ b2, const float* __restrict__ m2,
    const float* __restrict__ v2, const float* __restrict__ W3,
    float* __restrict__ out) {
    __shared__ float W2T[1024];   // [c][o], BN2 scale folded
    __shared__ float W3T[2048];   // [c][o]
    __shared__ float sh2s[32];
    __shared__ __align__(16) float Hs[4][640];   // per warp: h[k][lane]
    __shared__ __align__(16) float F2s[4][640];  // per warp: f2[k][lane]
    for (int i = threadIdx.x; i < 1024; i += 128) {
        int o = i & 31, cc = i >> 5;
        float s2 = g2[o] * rsqrtf(v2[o] + EPSV);
        W2T[cc * 32 + o] = W2[o * 32 + cc] * s2;
    }
    for (int i = threadIdx.x; i < 2048; i += 128) {
        int o = i & 63, cc = i >> 6;
        W3T[cc * 64 + o] = W3[o * 32 + cc];
    }
    if (threadIdx.x < 32) {
        int o = threadIdx.x;
        float s2 = g2[o] * rsqrtf(v2[o] + EPSV);
        sh2s[o] = fmaf(-m2[o], s2, b2[o]);
    }
    __syncthreads();
    int warp = threadIdx.x >> 5, lane = threadIdx.x & 31;
    u64 w2p[16], w3ap[16], w3bp[16];
    #pragma unroll
    for (int q = 0; q < 16; q++) {
        w2p[q]  = pack2(W2T[(2 * q) * 32 + lane],      W2T[(2 * q + 1) * 32 + lane]);
        w3ap[q] = pack2(W3T[(2 * q) * 64 + lane],      W3T[(2 * q + 1) * 64 + lane]);
        w3bp[q] = pack2(W3T[(2 * q) * 64 + 32 + lane], W3T[(2 * q + 1) * 64 + 32 + lane]);
    }
    float sh2 = sh2s[lane];
    #pragma unroll 1
    for (int pp = 0; pp < 8; pp++) {
        int point = (blockIdx.x * 4 + warp) * 8 + pp;
        int b = point >> 11, n = point & (NPT - 1);
        const float* YsB = g_Ys + (size_t)b * NPT * 32;
        float ps = g_Ps[point * 32 + lane];
        int myidx = 0;
        if (lane < KNNK) myidx = g_knn[point * KNNK + lane];
        // ---- phase A: gather + layer1 finish, stage all h ----
        int j0 = __shfl_sync(FULLMASK, myidx, 0);
        float ysn = YsB[j0 * 32 + lane];
        #pragma unroll 1
        for (int k = 0; k < KNNK; k++) {
            float ys = ysn;
            if (k + 1 < KNNK) {
                int jn = __shfl_sync(FULLMASK, myidx, k + 1);
                ysn = YsB[jn * 32 + lane];
            }
            float h = ys + ps;
            Hs[warp][k * 32 + lane] = fmaxf(h, 0.2f * h);
        }
        __syncwarp();
        // ---- phase B: f2[k] = lrelu(W2' h_k + sh2), split chains ----
        const u64* hp = (const u64*)Hs[warp];
        #pragma unroll 1
        for (int k = 0; k < KNNK; k++) {
            const u64* hk = hp + k * 16;
            u64 aa = 0, ab = 0;
            #pragma unroll
            for (int q = 0; q < 8; q++) {
                aa = fma2(w2p[q],     hk[q],     aa);
                ab = fma2(w2p[q + 8], hk[q + 8], ab);
            }
            float ax, ay; unpack2(add2(aa, ab), ax, ay);
            float acc = ax + ay + sh2;
            F2s[warp][k * 32 + lane] = fmaxf(acc, 0.2f * acc);
        }
        __syncwarp();
        // ---- phase C: layer3 + max over k, 4 split chains ----
        const u64* fp = (const u64*)F2s[warp];
        float a0 = NEGINF, a1 = NEGINF;
        #pragma unroll 1
        for (int k = 0; k < KNNK; k++) {
            const u64* fk = fp + k * 16;
            u64 t0a = 0, t0b = 0, t1a = 0, t1b = 0;
            #pragma unroll
            for (int q = 0; q < 8; q++) {
                u64 fv = fk[q];
                t0a = fma2(w3ap[q], fv, t0a);
                t1a = fma2(w3bp[q], fv, t1a);
                u64 fw = fk[q + 8];
                t0b = fma2(w3ap[q + 8], fw, t0b);
                t1b = fma2(w3bp[q + 8], fw, t1b);
            }
            float x0, y0, x1, y1;
            unpack2(add2(t0a, t0b), x0, y0);
            unpack2(add2(t1a, t1b), x1, y1);
            a0 = fmaxf(a0, x0 + y0);
            a1 = fmaxf(a1, x1 + y1);
        }
        // out[b][c][2n+u]: lane holds channel c=lane (u=0: a0, u=1: a1)
        float2* op = (float2*)(out + (size_t)(b * 32 + lane) * (2 * NPT) + 2 * n);
        *op = make_float2(a0, a1);
    }
}

extern "C" void kernel_launch(void* const* d_in, const int* in_sizes, int n_in,
                              void* d_out, int out_size) {
    const float* xyz = (const float*)d_in[0];
    const float* xf  = (const float*)d_in[1];
    const float* W1  = (const float*)d_in[2];
    const float* g1  = (const float*)d_in[3];
    const float* b1  = (const float*)d_in[4];
    const float* m1  = (const float*)d_in[5];
    const float* v1  = (const float*)d_in[6];
    const float* W2  = (const float*)d_in[7];
    const float* g2  = (const float*)d_in[8];
    const float* b2  = (const float*)d_in[9];
    const float* m2  = (const float*)d_in[10];
    const float* v2  = (const float*)d_in[11];
    const float* W3  = (const float*)d_in[12];
    float* out = (float*)d_out;

    knn_kernel<<<1024, 256>>>(xyz);
    pre_kernel<<<512, 256>>>(xf, W1, g1, b1, m1, v1);
    mlp_kernel<<<1024, 128>>>(W2, g2, b2, m2, v2, W3, out);
}

// round 6
// speedup vs baseline: 1.2120x; 1.2120x over previous
#include <cuda_runtime.h>
#include <stdint.h>

#define FULLMASK 0xFFFFFFFFu
#define NBATCH 16
#define NPT 2048
#define KNNK 20
#define EPSV 1e-5f
#define NEGINF (__int_as_float(0xff800000))

typedef unsigned long long u64;

// scratch (device globals: no allocation allowed)
__device__ float g_Ys[NBATCH * NPT * 32];
__device__ float g_Ps[NBATCH * NPT * 32];
__device__ int   g_knn[NBATCH * NPT * KNNK];

// ---- packed f32x2 helpers ----
__device__ __forceinline__ u64 pack2(float a, float b) {
    u64 r; asm("mov.b64 %0, {%1, %2};" : "=l"(r) : "f"(a), "f"(b)); return r;
}
__device__ __forceinline__ void unpack2(u64 v, float& a, float& b) {
    asm("mov.b64 {%0, %1}, %2;" : "=f"(a), "=f"(b) : "l"(v));
}
__device__ __forceinline__ u64 fma2(u64 a, u64 b, u64 c) {
    u64 d; asm("fma.rn.f32x2 %0, %1, %2, %3;" : "=l"(d) : "l"(a), "l"(b), "l"(c)); return d;
}
__device__ __forceinline__ u64 mul2(u64 a, u64 b) {
    u64 d; asm("mul.rn.f32x2 %0, %1, %2;" : "=l"(d) : "l"(a), "l"(b)); return d;
}
__device__ __forceinline__ u64 add2(u64 a, u64 b) {
    u64 d; asm("add.rn.f32x2 %0, %1, %2;" : "=l"(d) : "l"(a), "l"(b)); return d;
}

// monotone u32 transform of float (order-preserving)
__device__ __forceinline__ unsigned monot(float v) {
    unsigned u = __float_as_uint(v);
    return u ^ ((unsigned)(((int)u) >> 31) | 0x80000000u);
}

// branchless insert of (pd, j) into sorted-desc top-3; equal values keep the
// earlier (smaller-j) entry first, matching jax top_k tie order.
__device__ __forceinline__ void ins3b(float& v1, float& v2, float& v3,
                                      int& i1, int& i2, int& i3, float pd, int j) {
    bool g3 = pd > v3;
    bool g2 = pd > v2;
    bool g1 = pd > v1;
    v3 = g2 ? v2 : (g3 ? pd : v3);
    i3 = g2 ? i2 : (g3 ? j : i3);
    v2 = g1 ? v1 : (g2 ? pd : v2);
    i2 = g1 ? i1 : (g2 ? j : i2);
    v1 = g1 ? pd : v1;
    i1 = g1 ? j : i1;
}

// -------- KNN: warp/row, SoA smem, packed distances, dual branchless top-3 --------
__global__ __launch_bounds__(256) void knn_kernel(const float* __restrict__ xyz) {
    __shared__ __align__(16) float sx[NPT], sy[NPT], sz[NPT], snw[NPT];
    int b = blockIdx.x >> 6;          // 64 blocks per batch
    int chunk = blockIdx.x & 63;      // 32 rows per block
    const float* xb = xyz + (size_t)b * 3 * NPT;
    for (int i = threadIdx.x; i < NPT; i += 256) {
        float x = xb[i], y = xb[NPT + i], z = xb[2 * NPT + i];
        sx[i] = x; sy[i] = y; sz[i] = z;
        snw[i] = -(x * x + y * y + z * z);
    }
    __syncthreads();
    int warp = threadIdx.x >> 5, lane = threadIdx.x & 31;
    const u64 two2 = pack2(2.0f, 2.0f);
    #pragma unroll 1
    for (int rr = 0; rr < 4; rr++) {
        int n = chunk * 32 + warp * 4 + rr;
        float cx = sx[n], cy = sy[n], cz = sz[n];
        u64 cx2 = pack2(cx, cx), cy2 = pack2(cy, cy), cz2 = pack2(cz, cz);
        u64 bb2 = pack2(snw[n], snw[n]);
        // dual per-lane top-3 lists (even j -> A, odd j -> B)
        float va1 = NEGINF, va2 = NEGINF, va3 = NEGINF;
        float vb1 = NEGINF, vb2 = NEGINF, vb3 = NEGINF;
        int ia1 = 0, ia2 = 0, ia3 = 0, ib1 = 0, ib2 = 0, ib3 = 0;
        #pragma unroll 4
        for (int t = 0; t < 32; t++) {
            int jj = t * 64 + 2 * lane;
            u64 px = *(const u64*)(sx + jj);
            u64 py = *(const u64*)(sy + jj);
            u64 pz = *(const u64*)(sz + jj);
            u64 pw = *(const u64*)(snw + jj);
            u64 dot2 = fma2(cz2, pz, fma2(cy2, py, mul2(cx2, px)));
            u64 pd2 = fma2(two2, dot2, add2(pw, bb2));  // 2*dot - xx_i - xx_j
            float pl, ph; unpack2(pd2, pl, ph);
            ins3b(va1, va2, va3, ia1, ia2, ia3, pl, jj);
            ins3b(vb1, vb2, vb3, ib1, ib2, ib3, ph, jj + 1);
        }
        int myout = 0;
        #pragma unroll 1
        for (int r = 0; r < KNNK; r++) {
            // lazy merge: head = larger of the two list heads (tie -> smaller idx)
            bool pA = (va1 > vb1) || (va1 == vb1 && ia1 < ib1);
            float v1 = pA ? va1 : vb1;
            int   i1 = pA ? ia1 : ib1;
            unsigned key = monot(v1);
            unsigned mx = __reduce_max_sync(FULLMASK, key);
            unsigned lo = (key == mx) ? (unsigned)(NPT - 1 - i1) : 0u;
            unsigned lx = __reduce_max_sync(FULLMASK, lo);   // min index on value tie
            myout = (lane == r) ? (NPT - 1 - (int)lx) : myout;
            bool win = (key == mx) && (lo == lx);            // unique winner lane
            bool popA = win && pA, popB = win && !pA;
            va1 = popA ? va2 : va1; ia1 = popA ? ia2 : ia1;
            va2 = popA ? va3 : va2; ia2 = popA ? ia3 : ia2;
            va3 = popA ? NEGINF : va3;
            vb1 = popB ? vb2 : vb1; ib1 = popB ? ib2 : ib1;
            vb2 = popB ? vb3 : vb2; ib2 = popB ? ib3 : ib2;
            vb3 = popB ? NEGINF : vb3;
            // refill a list the moment it empties: all same-parity entries
            // lex-above (v1, i1) were already emitted from that list.
            if (popA && va1 == NEGINF) {   // rare (~2% of rows)
                float lastV = v1; int lastI = i1;
                #pragma unroll 4
                for (int t = 0; t < 32; t++) {
                    int jj = t * 64 + 2 * lane;
                    u64 px = *(const u64*)(sx + jj);
                    u64 py = *(const u64*)(sy + jj);
                    u64 pz = *(const u64*)(sz + jj);
                    u64 pw = *(const u64*)(snw + jj);
                    u64 dot2 = fma2(cz2, pz, fma2(cy2, py, mul2(cx2, px)));
                    u64 pd2 = fma2(two2, dot2, add2(pw, bb2));
                    float pl, ph; unpack2(pd2, pl, ph);
                    bool accl = (pl < lastV) || (pl == lastV && jj > lastI);
                    ins3b(va1, va2, va3, ia1, ia2, ia3, accl ? pl : NEGINF, jj);
                }
            }
            if (popB && vb1 == NEGINF) {
                float lastV = v1; int lastI = i1;
                #pragma unroll 4
                for (int t = 0; t < 32; t++) {
                    int jj = t * 64 + 2 * lane;
                    u64 px = *(const u64*)(sx + jj);
                    u64 py = *(const u64*)(sy + jj);
                    u64 pz = *(const u64*)(sz + jj);
                    u64 pw = *(const u64*)(snw + jj);
                    u64 dot2 = fma2(cz2, pz, fma2(cy2, py, mul2(cx2, px)));
                    u64 pd2 = fma2(two2, dot2, add2(pw, bb2));
                    float pl, ph; unpack2(pd2, pl, ph);
                    bool acch = (ph < lastV) || (ph == lastV && jj + 1 > lastI);
                    ins3b(vb1, vb2, vb3, ib1, ib2, ib3, acch ? ph : NEGINF, jj + 1);
                }
            }
        }
        if (lane < KNNK) g_knn[(b * NPT + n) * KNNK + lane] = myout;  // coalesced
    }
}

// ------------- precompute: Ys = s1*(W1a xf), Ps = s1*((W1b-W1a) xf) + shift1 -------------
__global__ __launch_bounds__(256) void pre_kernel(
    const float* __restrict__ xf, const float* __restrict__ W1,
    const float* __restrict__ g1, const float* __restrict__ b1,
    const float* __restrict__ m1, const float* __restrict__ v1) {
    __shared__ float W1T[128 * 32];  // [c][o] transposed for conflict-free LDS
    for (int i = threadIdx.x; i < 4096; i += 256) {
        int o = i & 31, cc = i >> 5;
        W1T[cc * 32 + o] = W1[o * 128 + cc];
    }
    __syncthreads();
    int warp = threadIdx.x >> 5, lane = threadIdx.x & 31;
    float s = g1[lane] * rsqrtf(v1[lane] + EPSV);
    float shift = fmaf(-m1[lane], s, b1[lane]);
    #pragma unroll 1
    for (int pp = 0; pp < 8; pp++) {
        int point = blockIdx.x * 64 + warp * 8 + pp;
        int b = point >> 11, n = point & (NPT - 1);
        const float* col = xf + (size_t)b * 64 * NPT + n;
        float y = 0.f, p = 0.f;
        #pragma unroll
        for (int cc = 0; cc < 64; cc++) {
            float xv = col[(size_t)cc * NPT];       // broadcast load
            float wa = W1T[cc * 32 + lane];         // W1[:,0:64]  (nbr - x part)
            float wb = W1T[(cc + 64) * 32 + lane];  // W1[:,64:128] (x part)
            y = fmaf(wa, xv, y);
            p = fmaf(wb - wa, xv, p);
        }
        g_Ys[point * 32 + lane] = y * s;
        g_Ps[point * 32 + lane] = fmaf(p, s, shift);
    }
}

// ------------- edge MLP: warp per point, lane = channel, FFMA2 packed GEMVs -------------
__global__ __launch_bounds__(128) void mlp_kernel(
    const float* __restrict__ W2, const float* __restrict__ g2,
    const float* __restrict__ b2, const float* __restrict__ m2,
    const float* __restrict__ v2, const float* __restrict__ W3,
    float* __restrict__ out) {
    __shared__ float W2T[1024];   // [c][o], BN2 scale folded
    __shared__ float W3T[2048];   // [c][o]
    __shared__ float sh2s[32];
    __shared__ __align__(16) float hbuf[4][32];
    __shared__ __align__(16) float fbuf[4][32];
    for (int i = threadIdx.x; i < 1024; i += 128) {
        int o = i & 31, cc = i >> 5;
        float s2 = g2[o] * rsqrtf(v2[o] + EPSV);
        W2T[cc * 32 + o] = W2[o * 32 + cc] * s2;
    }
    for (int i = threadIdx.x; i < 2048; i += 128) {
        int o = i & 63, cc = i >> 6;
        W3T[cc * 64 + o] = W3[o * 32 + cc];
    }
    if (threadIdx.x < 32) {
        int o = threadIdx.x;
        float s2 = g2[o] * rsqrtf(v2[o] + EPSV);
        sh2s[o] = fmaf(-m2[o], s2, b2[o]);
    }
    __syncthreads();
    int warp = threadIdx.x >> 5, lane = threadIdx.x & 31;
    // pre-packed weight pairs (consecutive input channels -> f32x2 lanes)
    u64 w2p[16], w3ap[16], w3bp[16];
    #pragma unroll
    for (int q = 0; q < 16; q++) {
        w2p[q]  = pack2(W2T[(2 * q) * 32 + lane],      W2T[(2 * q + 1) * 32 + lane]);
        w3ap[q] = pack2(W3T[(2 * q) * 64 + lane],      W3T[(2 * q + 1) * 64 + lane]);
        w3bp[q] = pack2(W3T[(2 * q) * 64 + 32 + lane], W3T[(2 * q + 1) * 64 + 32 + lane]);
    }
    float sh2 = sh2s[lane];
    const u64* h8 = (const u64*)hbuf[warp];
    const u64* f8 = (const u64*)fbuf[warp];
    #pragma unroll 1
    for (int pp = 0; pp < 8; pp++) {
        int point = (blockIdx.x * 4 + warp) * 8 + pp;
        int b = point >> 11, n = point & (NPT - 1);
        const float* YsB = g_Ys + (size_t)b * NPT * 32;
        float ps = g_Ps[point * 32 + lane];
        int myidx = 0;
        if (lane < KNNK) myidx = g_knn[point * KNNK + lane];
        int j0 = __shfl_sync(FULLMASK, myidx, 0);
        float ysn = YsB[j0 * 32 + lane];   // software-pipelined gather
        float a0 = NEGINF, a1 = NEGINF;
        #pragma unroll 1
        for (int k = 0; k < KNNK; k++) {
            float ys = ysn;
            if (k + 1 < KNNK) {
                int jn = __shfl_sync(FULLMASK, myidx, k + 1);
                ysn = YsB[jn * 32 + lane];
            }
            float h = ys + ps;
            h = fmaxf(h, 0.2f * h);          // leaky relu
            hbuf[warp][lane] = h;
            __syncwarp();
            u64 acc2 = 0;
            #pragma unroll
            for (int q = 0; q < 16; q++)     // f2 = lrelu(W2' h + sh2), packed
                acc2 = fma2(w2p[q], h8[q], acc2);
            float ax, ay;
            unpack2(acc2, ax, ay);
            float acc = ax + ay + sh2;
            acc = fmaxf(acc, 0.2f * acc);
            fbuf[warp][lane] = acc;
            __syncwarp();
            u64 t0p = 0, t1p = 0;
            #pragma unroll
            for (int q = 0; q < 16; q++) {   // f3 = W3 f2 (2 rows per lane), packed
                u64 fv = f8[q];
                t0p = fma2(w3ap[q], fv, t0p);
                t1p = fma2(w3bp[q], fv, t1p);
            }
            float t0x, t0y, t1x, t1y;
            unpack2(t0p, t0x, t0y);
            unpack2(t1p, t1x, t1y);
            a0 = fmaxf(a0, t0x + t0y);
            a1 = fmaxf(a1, t1x + t1y);
        }
        // out[b][c][2n+u] = fmax[b][u*32+c][n]; lane holds c=lane (u=0: a0, u=1: a1)
        float2* op = (float2*)(out + (size_t)(b * 32 + lane) * (2 * NPT) + 2 * n);
        *op = make_float2(a0, a1);
    }
}

extern "C" void kernel_launch(void* const* d_in, const int* in_sizes, int n_in,
                              void* d_out, int out_size) {
    const float* xyz = (const float*)d_in[0];
    const float* xf  = (const float*)d_in[1];
    const float* W1  = (const float*)d_in[2];
    const float* g1  = (const float*)d_in[3];
    const float* b1  = (const float*)d_in[4];
    const float* m1  = (const float*)d_in[5];
    const float* v1  = (const float*)d_in[6];
    const float* W2  = (const float*)d_in[7];
    const float* g2  = (const float*)d_in[8];
    const float* b2  = (const float*)d_in[9];
    const float* m2  = (const float*)d_in[10];
    const float* v2  = (const float*)d_in[11];
    const float* W3  = (const float*)d_in[12];
    float* out = (float*)d_out;

    knn_kernel<<<1024, 256>>>(xyz);
    pre_kernel<<<512, 256>>>(xf, W1, g1, b1, m1, v1);
    mlp_kernel<<<1024, 128>>>(W2, g2, b2, m2, v2, W3, out);
}

// round 7
// speedup vs baseline: 1.2131x; 1.0008x over previous
#include <cuda_runtime.h>
#include <stdint.h>

#define FULLMASK 0xFFFFFFFFu
#define NBATCH 16
#define NPT 2048
#define KNNK 20
#define EPSV 1e-5f
#define NEGINF (__int_as_float(0xff800000))

typedef unsigned long long u64;

// scratch (device globals: no allocation allowed)
__device__ float g_Ys[NBATCH * NPT * 32];
__device__ float g_Ps[NBATCH * NPT * 32];
__device__ int   g_knn[NBATCH * NPT * KNNK];

// ---- packed f32x2 helpers ----
__device__ __forceinline__ u64 pack2(float a, float b) {
    u64 r; asm("mov.b64 %0, {%1, %2};" : "=l"(r) : "f"(a), "f"(b)); return r;
}
__device__ __forceinline__ void unpack2(u64 v, float& a, float& b) {
    asm("mov.b64 {%0, %1}, %2;" : "=f"(a), "=f"(b) : "l"(v));
}
__device__ __forceinline__ u64 fma2(u64 a, u64 b, u64 c) {
    u64 d; asm("fma.rn.f32x2 %0, %1, %2, %3;" : "=l"(d) : "l"(a), "l"(b), "l"(c)); return d;
}
__device__ __forceinline__ u64 mul2(u64 a, u64 b) {
    u64 d; asm("mul.rn.f32x2 %0, %1, %2;" : "=l"(d) : "l"(a), "l"(b)); return d;
}
__device__ __forceinline__ u64 add2(u64 a, u64 b) {
    u64 d; asm("add.rn.f32x2 %0, %1, %2;" : "=l"(d) : "l"(a), "l"(b)); return d;
}

// monotone u32 transform of float (order-preserving)
__device__ __forceinline__ unsigned monot(float v) {
    unsigned u = __float_as_uint(v);
    return u ^ ((unsigned)(((int)u) >> 31) | 0x80000000u);
}

// branchless insert of (pd, j) into sorted-desc top-3; equal values keep the
// earlier (smaller-j) entry first, matching jax top_k tie order.
__device__ __forceinline__ void ins3b(float& v1, float& v2, float& v3,
                                      int& i1, int& i2, int& i3, float pd, int j) {
    bool g3 = pd > v3;
    bool g2 = pd > v2;
    bool g1 = pd > v1;
    v3 = g2 ? v2 : (g3 ? pd : v3);
    i3 = g2 ? i2 : (g3 ? j : i3);
    v2 = g1 ? v1 : (g2 ? pd : v2);
    i2 = g1 ? i1 : (g2 ? j : i2);
    v1 = g1 ? pd : v1;
    i1 = g1 ? j : i1;
}

// -------- KNN: warp/row, SoA smem, packed distances, dual branchless top-3 --------
// block=512 (16 warps), grid=512: 3 CTAs/SM (reg-limited) = 48 warps = 75% occ
__global__ __launch_bounds__(512) void knn_kernel(const float* __restrict__ xyz) {
    __shared__ __align__(16) float sx[NPT], sy[NPT], sz[NPT], snw[NPT];
    int b = blockIdx.x >> 5;          // 32 blocks per batch
    int chunk = blockIdx.x & 31;      // 64 rows per block
    const float* xb = xyz + (size_t)b * 3 * NPT;
    for (int i = threadIdx.x; i < NPT; i += 512) {
        float x = xb[i], y = xb[NPT + i], z = xb[2 * NPT + i];
        sx[i] = x; sy[i] = y; sz[i] = z;
        snw[i] = -(x * x + y * y + z * z);
    }
    __syncthreads();
    int warp = threadIdx.x >> 5, lane = threadIdx.x & 31;
    const u64 two2 = pack2(2.0f, 2.0f);
    #pragma unroll 1
    for (int rr = 0; rr < 4; rr++) {
        int n = chunk * 64 + warp * 4 + rr;
        float cx = sx[n], cy = sy[n], cz = sz[n];
        u64 cx2 = pack2(cx, cx), cy2 = pack2(cy, cy), cz2 = pack2(cz, cz);
        u64 bb2 = pack2(snw[n], snw[n]);
        // dual per-lane top-3 lists (even j -> A, odd j -> B)
        float va1 = NEGINF, va2 = NEGINF, va3 = NEGINF;
        float vb1 = NEGINF, vb2 = NEGINF, vb3 = NEGINF;
        int ia1 = 0, ia2 = 0, ia3 = 0, ib1 = 0, ib2 = 0, ib3 = 0;
        #pragma unroll 4
        for (int t = 0; t < 32; t++) {
            int jj = t * 64 + 2 * lane;
            u64 px = *(const u64*)(sx + jj);
            u64 py = *(const u64*)(sy + jj);
            u64 pz = *(const u64*)(sz + jj);
            u64 pw = *(const u64*)(snw + jj);
            u64 dot2 = fma2(cz2, pz, fma2(cy2, py, mul2(cx2, px)));
            u64 pd2 = fma2(two2, dot2, add2(pw, bb2));  // 2*dot - xx_i - xx_j
            float pl, ph; unpack2(pd2, pl, ph);
            ins3b(va1, va2, va3, ia1, ia2, ia3, pl, jj);
            ins3b(vb1, vb2, vb3, ib1, ib2, ib3, ph, jj + 1);
        }
        int myout = 0;
        #pragma unroll 1
        for (int r = 0; r < KNNK; r++) {
            // lazy merge: head = larger of the two list heads (tie -> smaller idx)
            bool pA = (va1 > vb1) || (va1 == vb1 && ia1 < ib1);
            float v1 = pA ? va1 : vb1;
            int   i1 = pA ? ia1 : ib1;
            unsigned key = monot(v1);
            unsigned mx = __reduce_max_sync(FULLMASK, key);
            unsigned lo = (key == mx) ? (unsigned)(NPT - 1 - i1) : 0u;
            unsigned lx = __reduce_max_sync(FULLMASK, lo);   // min index on value tie
            myout = (lane == r) ? (NPT - 1 - (int)lx) : myout;
            bool win = (key == mx) && (lo == lx);            // unique winner lane
            bool popA = win && pA, popB = win && !pA;
            va1 = popA ? va2 : va1; ia1 = popA ? ia2 : ia1;
            va2 = popA ? va3 : va2; ia2 = popA ? ia3 : ia2;
            va3 = popA ? NEGINF : va3;
            vb1 = popB ? vb2 : vb1; ib1 = popB ? ib2 : ib1;
            vb2 = popB ? vb3 : vb2; ib2 = popB ? ib3 : ib2;
            vb3 = popB ? NEGINF : vb3;
            // refill a list the moment it empties: all same-parity entries
            // lex-above (v1, i1) were already emitted from that list.
            if (popA && va1 == NEGINF) {   // rare (~2% of rows)
                float lastV = v1; int lastI = i1;
                #pragma unroll 4
                for (int t = 0; t < 32; t++) {
                    int jj = t * 64 + 2 * lane;
                    u64 px = *(const u64*)(sx + jj);
                    u64 py = *(const u64*)(sy + jj);
                    u64 pz = *(const u64*)(sz + jj);
                    u64 pw = *(const u64*)(snw + jj);
                    u64 dot2 = fma2(cz2, pz, fma2(cy2, py, mul2(cx2, px)));
                    u64 pd2 = fma2(two2, dot2, add2(pw, bb2));
                    float pl, ph; unpack2(pd2, pl, ph);
                    bool accl = (pl < lastV) || (pl == lastV && jj > lastI);
                    ins3b(va1, va2, va3, ia1, ia2, ia3, accl ? pl : NEGINF, jj);
                }
            }
            if (popB && vb1 == NEGINF) {
                float lastV = v1; int lastI = i1;
                #pragma unroll 4
                for (int t = 0; t < 32; t++) {
                    int jj = t * 64 + 2 * lane;
                    u64 px = *(const u64*)(sx + jj);
                    u64 py = *(const u64*)(sy + jj);
                    u64 pz = *(const u64*)(sz + jj);
                    u64 pw = *(const u64*)(snw + jj);
                    u64 dot2 = fma2(cz2, pz, fma2(cy2, py, mul2(cx2, px)));
                    u64 pd2 = fma2(two2, dot2, add2(pw, bb2));
                    float pl, ph; unpack2(pd2, pl, ph);
                    bool acch = (ph < lastV) || (ph == lastV && jj + 1 > lastI);
                    ins3b(vb1, vb2, vb3, ib1, ib2, ib3, acch ? ph : NEGINF, jj + 1);
                }
            }
        }
        if (lane < KNNK) g_knn[(b * NPT + n) * KNNK + lane] = myout;  // coalesced
    }
}

// ------------- precompute: Ys = s1*(W1a xf), Ps = s1*((W1b-W1a) xf) + shift1 -------------
__global__ __launch_bounds__(256) void pre_kernel(
    const float* __restrict__ xf, const float* __restrict__ W1,
    const float* __restrict__ g1, const float* __restrict__ b1,
    const float* __restrict__ m1, const float* __restrict__ v1) {
    __shared__ float W1T[128 * 32];  // [c][o] transposed for conflict-free LDS
    for (int i = threadIdx.x; i < 4096; i += 256) {
        int o = i & 31, cc = i >> 5;
        W1T[cc * 32 + o] = W1[o * 128 + cc];
    }
    __syncthreads();
    int warp = threadIdx.x >> 5, lane = threadIdx.x & 31;
    float s = g1[lane] * rsqrtf(v1[lane] + EPSV);
    float shift = fmaf(-m1[lane], s, b1[lane]);
    #pragma unroll 1
    for (int pp = 0; pp < 8; pp++) {
        int point = blockIdx.x * 64 + warp * 8 + pp;
        int b = point >> 11, n = point & (NPT - 1);
        const float* col = xf + (size_t)b * 64 * NPT + n;
        float y = 0.f, p = 0.f;
        #pragma unroll
        for (int cc = 0; cc < 64; cc++) {
            float xv = col[(size_t)cc * NPT];       // broadcast load
            float wa = W1T[cc * 32 + lane];         // W1[:,0:64]  (nbr - x part)
            float wb = W1T[(cc + 64) * 32 + lane];  // W1[:,64:128] (x part)
            y = fmaf(wa, xv, y);
            p = fmaf(wb - wa, xv, p);
        }
        g_Ys[point * 32 + lane] = y * s;
        g_Ps[point * 32 + lane] = fmaf(p, s, shift);
    }
}

// ---- edge MLP: warp per 2 points interleaved (double ILP), FFMA2 packed GEMVs ----
__global__ __launch_bounds__(128) void mlp_kernel(
    const float* __restrict__ W2, const float* __restrict__ g2,
    const float* __restrict__ b2, const float* __restrict__ m2,
    const float* __restrict__ v2, const float* __restrict__ W3,
    float* __restrict__ out) {
    __shared__ float W2T[1024];   // [c][o], BN2 scale folded
    __shared__ float W3T[2048];   // [c][o]
    __shared__ float sh2s[32];
    __shared__ __align__(16) float hbuf[4][2][32];
    __shared__ __align__(16) float fbuf[4][2][32];
    for (int i = threadIdx.x; i < 1024; i += 128) {
        int o = i & 31, cc = i >> 5;
        float s2 = g2[o] * rsqrtf(v2[o] + EPSV);
        W2T[cc * 32 + o] = W2[o * 32 + cc] * s2;
    }
    for (int i = threadIdx.x; i < 2048; i += 128) {
        int o = i & 63, cc = i >> 6;
        W3T[cc * 64 + o] = W3[o * 32 + cc];
    }
    if (threadIdx.x < 32) {
        int o = threadIdx.x;
        float s2 = g2[o] * rsqrtf(v2[o] + EPSV);
        sh2s[o] = fmaf(-m2[o], s2, b2[o]);
    }
    __syncthreads();
    int warp = threadIdx.x >> 5, lane = threadIdx.x & 31;
    // pre-packed weight pairs (consecutive input channels -> f32x2 lanes)
    u64 w2p[16], w3ap[16], w3bp[16];
    #pragma unroll
    for (int q = 0; q < 16; q++) {
        w2p[q]  = pack2(W2T[(2 * q) * 32 + lane],      W2T[(2 * q + 1) * 32 + lane]);
        w3ap[q] = pack2(W3T[(2 * q) * 64 + lane],      W3T[(2 * q + 1) * 64 + lane]);
        w3bp[q] = pack2(W3T[(2 * q) * 64 + 32 + lane], W3T[(2 * q + 1) * 64 + 32 + lane]);
    }
    float sh2 = sh2s[lane];
    const u64* h8A = (const u64*)hbuf[warp][0];
    const u64* h8B = (const u64*)hbuf[warp][1];
    const u64* f8A = (const u64*)fbuf[warp][0];
    const u64* f8B = (const u64*)fbuf[warp][1];
    #pragma unroll 1
    for (int pp = 0; pp < 4; pp++) {
        int pointA = (blockIdx.x * 4 + warp) * 8 + 2 * pp;  // even
        int pointB = pointA + 1;
        int b = pointA >> 11, nA = pointA & (NPT - 1);
        const float* YsB = g_Ys + (size_t)b * NPT * 32;
        float psA = g_Ps[pointA * 32 + lane];
        float psB = g_Ps[pointB * 32 + lane];
        int idxA = 0, idxB = 0;
        if (lane < KNNK) {
            idxA = g_knn[pointA * KNNK + lane];
            idxB = g_knn[pointB * KNNK + lane];
        }
        int jA = __shfl_sync(FULLMASK, idxA, 0);
        int jB = __shfl_sync(FULLMASK, idxB, 0);
        float ysnA = YsB[jA * 32 + lane];   // software-pipelined gathers
        float ysnB = YsB[jB * 32 + lane];
        float a0A = NEGINF, a1A = NEGINF, a0B = NEGINF, a1B = NEGINF;
        #pragma unroll 1
        for (int k = 0; k < KNNK; k++) {
            float ysA = ysnA, ysB_ = ysnB;
            if (k + 1 < KNNK) {
                int jnA = __shfl_sync(FULLMASK, idxA, k + 1);
                int jnB = __shfl_sync(FULLMASK, idxB, k + 1);
                ysnA = YsB[jnA * 32 + lane];
                ysnB = YsB[jnB * 32 + lane];
            }
            float hA = ysA + psA;  hA = fmaxf(hA, 0.2f * hA);
            float hB = ysB_ + psB; hB = fmaxf(hB, 0.2f * hB);
            hbuf[warp][0][lane] = hA;
            hbuf[warp][1][lane] = hB;
            __syncwarp();
            u64 accA = 0, accB = 0;
            #pragma unroll
            for (int q = 0; q < 16; q++) {   // two independent 16-chains
                accA = fma2(w2p[q], h8A[q], accA);
                accB = fma2(w2p[q], h8B[q], accB);
            }
            float ax, ay, bx, by;
            unpack2(accA, ax, ay);
            unpack2(accB, bx, by);
            float fA = ax + ay + sh2; fA = fmaxf(fA, 0.2f * fA);
            float fB = bx + by + sh2; fB = fmaxf(fB, 0.2f * fB);
            fbuf[warp][0][lane] = fA;
            fbuf[warp][1][lane] = fB;
            __syncwarp();
            u64 t0A = 0, t1A = 0, t0B = 0, t1B = 0;  // four independent chains
            #pragma unroll
            for (int q = 0; q < 16; q++) {
                u64 fvA = f8A[q], fvB = f8B[q];
                t0A = fma2(w3ap[q], fvA, t0A);
                t1A = fma2(w3bp[q], fvA, t1A);
                t0B = fma2(w3ap[q], fvB, t0B);
                t1B = fma2(w3bp[q], fvB, t1B);
            }
            float x0, y0, x1, y1;
            unpack2(t0A, x0, y0); unpack2(t1A, x1, y1);
            a0A = fmaxf(a0A, x0 + y0); a1A = fmaxf(a1A, x1 + y1);
            unpack2(t0B, x0, y0); unpack2(t1B, x1, y1);
            a0B = fmaxf(a0B, x0 + y0); a1B = fmaxf(a1B, x1 + y1);
        }
        // out[b][c][2n+u]: points A,B adjacent -> one 16B store (nA even)
        float4* op = (float4*)(out + (size_t)(b * 32 + lane) * (2 * NPT) + 2 * nA);
        *op = make_float4(a0A, a1A, a0B, a1B);
    }
}

extern "C" void kernel_launch(void* const* d_in, const int* in_sizes, int n_in,
                              void* d_out, int out_size) {
    const float* xyz = (const float*)d_in[0];
    const float* xf  = (const float*)d_in[1];
    const float* W1  = (const float*)d_in[2];
    const float* g1  = (const float*)d_in[3];
    const float* b1  = (const float*)d_in[4];
    const float* m1  = (const float*)d_in[5];
    const float* v1  = (const float*)d_in[6];
    const float* W2  = (const float*)d_in[7];
    const float* g2  = (const float*)d_in[8];
    const float* b2  = (const float*)d_in[9];
    const float* m2  = (const float*)d_in[10];
    const float* v2  = (const float*)d_in[11];
    const float* W3  = (const float*)d_in[12];
    float* out = (float*)d_out;

    knn_kernel<<<512, 512>>>(xyz);
    pre_kernel<<<512, 256>>>(xf, W1, g1, b1, m1, v1);
    mlp_kernel<<<1024, 128>>>(W2, g2, b2, m2, v2, W3, out);
}